// round 8
// baseline (speedup 1.0000x reference)
#include <cuda_runtime.h>

#define BB 32
#define TT 512
#define DD 384
#define ML 4096
#define D4 (DD / 4)        // 96 float4 per row
#define NG  (TT / 4)       // 128 token-groups per batch
#define NBLK (BB * NG)     // 4096 blocks total

// Block-wide sum over 96 threads (3 warps); all threads get the result.
__device__ __forceinline__ int block_sum96(int v, int* s3) {
    #pragma unroll
    for (int off = 16; off > 0; off >>= 1)
        v += __shfl_down_sync(0xffffffffu, v, off);
    const int w = threadIdx.x >> 5;
    if ((threadIdx.x & 31) == 0) s3[w] = v;
    __syncthreads();
    return s3[0] + s3[1] + s3[2];
}

// Single block type: 96 threads (threadIdx.x == c4), 4 tokens per block.
//  1) issue 4 address-static x row loads (MLP=4, hidden latency)
//  2) one packed reduce over dur[b][*]: prefix (q<g) in hi16, total in lo16
//  3) scatter each row dur times to consecutive frames
//  4) write mel_pos for this block's 32-frame span
//  5) zero-fill this block's 1/NG share of [total, ML)
__global__ __launch_bounds__(96) void lr_fused(const float4* __restrict__ x,
                                               const int*    __restrict__ dur,
                                               float4* __restrict__ out,
                                               float4* __restrict__ mel4) {
    __shared__ int s3[3];
    const int c4 = threadIdx.x;
    const int tb = blockIdx.x;
    const int b  = tb >> 7;            // NG = 128 groups per batch
    const int g  = tb & 127;
    const int t0 = g << 2;

    // (1) streaming x loads — addresses depend only on blockIdx
    const float4* xr = x + ((size_t)b * TT + t0) * D4 + c4;
    const float4 v0 = __ldg(xr);
    const float4 v1 = __ldg(xr + D4);
    const float4 v2 = __ldg(xr + 2 * D4);
    const float4 v3 = __ldg(xr + 3 * D4);

    // (2) packed prefix+total reduce over 128 int4 (L1/L2 hits, overlapped)
    const int4* dq = reinterpret_cast<const int4*>(dur + b * TT);
    int part = 0;
    {
        const int4 u = __ldg(&dq[c4]);
        const int s = u.x + u.y + u.z + u.w;
        part = s + ((c4 < g) ? (s << 16) : 0);
        if (c4 < 32) {
            const int4 u2 = __ldg(&dq[c4 + 96]);
            const int s2 = u2.x + u2.y + u2.z + u2.w;
            part += s2 + ((c4 + 96 < g) ? (s2 << 16) : 0);
        }
    }
    const int4 dv = __ldg(&dq[g]);     // this group's 4 durations
    const int red = block_sum96(part, s3);
    const int total  = red & 0xffff;   // sums <= 3584, no field overflow
    const int prefix = red >> 16;

    // (3) scatter
    const int s0 = prefix;
    const int s1 = s0 + dv.x;
    const int s2 = s1 + dv.y;
    const int s3s = s2 + dv.z;
    float4* ob = out + (size_t)b * ML * D4 + c4;
    {
        float4* o = ob + (size_t)s0 * D4;
        for (int j = 0; j < dv.x; ++j) __stcs(o + (size_t)j * D4, v0);
    }
    {
        float4* o = ob + (size_t)s1 * D4;
        for (int j = 0; j < dv.y; ++j) __stcs(o + (size_t)j * D4, v1);
    }
    {
        float4* o = ob + (size_t)s2 * D4;
        for (int j = 0; j < dv.z; ++j) __stcs(o + (size_t)j * D4, v2);
    }
    {
        float4* o = ob + (size_t)s3s * D4;
        for (int j = 0; j < dv.w; ++j) __stcs(o + (size_t)j * D4, v3);
    }

    // (4) mel_pos for frames [g*32, g*32+32): threads 0..7, one float4 each
    if (c4 < 8) {
        const int f = (g << 5) + (c4 << 2);
        float4 m;
        m.x = (f     < total) ? (float)(f + 1) : 0.0f;
        m.y = (f + 1 < total) ? (float)(f + 2) : 0.0f;
        m.z = (f + 2 < total) ? (float)(f + 3) : 0.0f;
        m.w = (f + 3 < total) ? (float)(f + 4) : 0.0f;
        mel4[(b * ML + f) >> 2] = m;
    }

    // (5) zero-fill this block's share of [total, ML)
    const int nz    = ML - total;              // >= 512 (total <= 3584)
    const int chunk = (nz + NG - 1) >> 7;      // ceil(nz / 128)
    const int z0    = total + g * chunk;
    const int z1    = (z0 + chunk < ML) ? (z0 + chunk) : ML;
    if (z0 < z1) {
        const float4 z = make_float4(0.0f, 0.0f, 0.0f, 0.0f);
        float4* o = out + ((size_t)b * ML + z0) * D4 + c4;
        for (int f = z0; f < z1; ++f, o += D4) __stcs(o, z);
    }
}

extern "C" void kernel_launch(void* const* d_in, const int* in_sizes, int n_in,
                              void* d_out, int out_size) {
    const float* x   = (const float*)d_in[0];
    const int*   dur = (const int*)d_in[1];

    float* out = (float*)d_out;                 // [B, ML, D] f32
    float* mel = out + (size_t)BB * ML * DD;    // [B, ML] written as float

    lr_fused<<<NBLK, 96>>>((const float4*)x, dur,
                           (float4*)out, (float4*)mel);
}

// round 9
// speedup vs baseline: 1.0344x; 1.0344x over previous
#include <cuda_runtime.h>

#define BB 32
#define TT 512
#define DD 384
#define ML 4096
#define D4 (DD / 4)        // 96 float4 per row
#define NTOKBLK (BB * TT / 4)   // 4096 token blocks (4 tokens each)
#define NZB     64              // frame blocks per batch
#define NCHUNK  8               // 8-row chunks served per frame block
#define NZBLK   (BB * NZB)      // 2048 frame blocks

// Block-wide sum of per-thread 'v' over 96 threads (3 warps).
__device__ __forceinline__ int block_sum96(int v, int* s3) {
    #pragma unroll
    for (int off = 16; off > 0; off >>= 1)
        v += __shfl_down_sync(0xffffffffu, v, off);
    const int w = threadIdx.x >> 5;
    if ((threadIdx.x & 31) == 0) s3[w] = v;
    __syncthreads();
    return s3[0] + s3[1] + s3[2];
}

// 96 threads per block (threadIdx.x == c4).
//  blocks [0, NTOKBLK): 4 tokens; address-static x loads (MLP=4), in-block
//    prefix reduce hidden under load latency; each row stored dur times.
//  blocks [NTOKBLK, +NZBLK): reduce total ONCE, then serve 8 strided 8-row
//    chunks: mel_pos + zero-fill where f >= total.
__global__ __launch_bounds__(96) void lr_fused(const float4* __restrict__ x,
                                               const int*    __restrict__ dur,
                                               float4* __restrict__ out,
                                               float4* __restrict__ mel4) {
    __shared__ int s3[3];
    const int c4 = threadIdx.x;

    if (blockIdx.x < NTOKBLK) {
        const int tb = blockIdx.x;
        const int b  = tb >> 7;             // TT/4 = 128 token-groups/batch
        const int t0 = (tb & 127) << 2;

        // Streaming x loads: addresses depend only on blockIdx -> issue now.
        const float4* xr = x + ((size_t)b * TT + t0) * D4 + c4;
        const float4 v0 = __ldg(xr);
        const float4 v1 = __ldg(xr + D4);
        const float4 v2 = __ldg(xr + 2 * D4);
        const float4 v3 = __ldg(xr + 3 * D4);

        // Prefix over dur[b][0..t0) (overlapped with x loads).
        const int4* dq = reinterpret_cast<const int4*>(dur + b * TT);
        const int nq = t0 >> 2;             // int4s before this group
        int part = 0;
        for (int q = c4; q < nq; q += 96) {
            const int4 u = __ldg(&dq[q]);
            part += u.x + u.y + u.z + u.w;
        }
        const int4 dv = __ldg(&dq[nq]);     // d0..d3
        const int prefix = block_sum96(part, s3);

        const int s0 = prefix;
        const int s1 = s0 + dv.x;
        const int s2 = s1 + dv.y;
        const int s3s = s2 + dv.z;

        float4* ob = out + (size_t)b * ML * D4 + c4;
        {
            float4* o = ob + (size_t)s0 * D4;
            for (int j = 0; j < dv.x; ++j) __stcs(o + (size_t)j * D4, v0);
        }
        {
            float4* o = ob + (size_t)s1 * D4;
            for (int j = 0; j < dv.y; ++j) __stcs(o + (size_t)j * D4, v1);
        }
        {
            float4* o = ob + (size_t)s2 * D4;
            for (int j = 0; j < dv.z; ++j) __stcs(o + (size_t)j * D4, v2);
        }
        {
            float4* o = ob + (size_t)s3s * D4;
            for (int j = 0; j < dv.w; ++j) __stcs(o + (size_t)j * D4, v3);
        }
    } else {
        const int zb = blockIdx.x - NTOKBLK;
        const int b  = zb >> 6;             // NZB = 64 blocks per batch
        const int g0 = zb & 63;

        // total = sum of all 512 durations (128 int4s; L1/L2 hits). Once.
        const int4* dq = reinterpret_cast<const int4*>(dur + b * TT);
        int part = 0;
        {
            const int4 u = __ldg(&dq[c4]);
            part = u.x + u.y + u.z + u.w;
            if (c4 < 32) {
                const int4 u2 = __ldg(&dq[c4 + 96]);
                part += u2.x + u2.y + u2.z + u2.w;
            }
        }
        const int total = block_sum96(part, s3);

        const float4 z = make_float4(0.0f, 0.0f, 0.0f, 0.0f);

        #pragma unroll
        for (int k = 0; k < NCHUNK; ++k) {
            const int f0 = (g0 + k * NZB) << 3;   // strided 8-row chunk

            if (c4 < 2) {                          // mel_pos for this chunk
                const int f = f0 + c4 * 4;
                float4 m;
                m.x = (f     < total) ? (float)(f + 1) : 0.0f;
                m.y = (f + 1 < total) ? (float)(f + 2) : 0.0f;
                m.z = (f + 2 < total) ? (float)(f + 3) : 0.0f;
                m.w = (f + 3 < total) ? (float)(f + 4) : 0.0f;
                mel4[(b * ML + f) >> 2] = m;
            }

            if (f0 + 8 <= total) continue;         // fully valid chunk

            float4* o = out + ((size_t)b * ML + f0) * D4 + c4;
            const int jlo = (total > f0) ? (total - f0) : 0;
            #pragma unroll
            for (int j = 0; j < 8; ++j) {
                if (j >= jlo) __stcs(o + (size_t)j * D4, z);
            }
        }
    }
}

extern "C" void kernel_launch(void* const* d_in, const int* in_sizes, int n_in,
                              void* d_out, int out_size) {
    const float* x   = (const float*)d_in[0];
    const int*   dur = (const int*)d_in[1];

    float* out = (float*)d_out;                 // [B, ML, D] f32
    float* mel = out + (size_t)BB * ML * DD;    // [B, ML] written as float

    lr_fused<<<NTOKBLK + NZBLK, 96>>>((const float4*)x, dur,
                                      (float4*)out, (float4*)mel);
}